// round 15
// baseline (speedup 1.0000x reference)
#include <cuda_runtime.h>
#include <math.h>

#define QN 4
#define RFN 32
#define NSS 4
#define CNN 18
#define HH 64
#define WW 64
#define HWSZ 4096
#define KNN 4

#define OFF_POS 0
#define OFF_SCL 8
#define OFF_SCORES 12
#define OFF_SCALES (12 + 16384)
#define OFF_OFFS (12 + 32768)

// ---------------- f32x2 helpers ----------------
__device__ __forceinline__ unsigned long long pk2(float x) {
    unsigned long long r;
    asm("mov.b64 %0, {%1, %1};" : "=l"(r) : "f"(x));
    return r;
}
__device__ __forceinline__ unsigned long long pk2b(float a, float b) {
    unsigned long long r;
    asm("mov.b64 %0, {%1, %2};" : "=l"(r) : "f"(a), "f"(b));
    return r;
}
__device__ __forceinline__ unsigned long long fma2(unsigned long long a, unsigned long long b,
                                                   unsigned long long c) {
    unsigned long long d;
    asm("fma.rn.f32x2 %0, %1, %2, %3;" : "=l"(d) : "l"(a), "l"(b), "l"(c));
    return d;
}
__device__ __forceinline__ float2 up2(unsigned long long v) {
    float lo, hi;
    asm("mov.b64 {%0, %1}, %2;" : "=f"(lo), "=f"(hi) : "l"(v));
    return make_float2(lo, hi);
}
union F4U2 { float4 f4; unsigned long long u[2]; };

// ---------------- device scratch ----------------
__device__ float g_scale[QN * RFN * NSS * CNN];
__device__ float g_shift[QN * RFN * NSS * CNN];
__device__ float g_ys[QN * NSS * 64 * HWSZ];
__device__ float g_yc[QN * NSS * 64 * HWSZ];
__device__ float g_xs[QN * 64 * HWSZ];
__device__ float g_xc[QN * 64 * HWSZ];
__device__ float g_t1[3 * QN * 64 * HWSZ];
__device__ float g_t2[3 * QN * 64 * HWSZ];

// ---------------- 1) per-channel mean / rstd ----------------
__global__ void stats_kernel(const float* __restrict__ corr) {
    int b = blockIdx.x;
    int tid = threadIdx.x;
    const float* p = corr + (size_t)b * HWSZ;
    double s = 0.0, ss = 0.0;
    for (int i = tid; i < HWSZ; i += 256) {
        float v = p[i];
        s += v;
        ss += (double)v * v;
    }
    for (int o = 16; o > 0; o >>= 1) {
        s += __shfl_down_sync(0xffffffffu, s, o);
        ss += __shfl_down_sync(0xffffffffu, ss, o);
    }
    __shared__ double ws[8], wss[8];
    if ((tid & 31) == 0) { ws[tid >> 5] = s; wss[tid >> 5] = ss; }
    __syncthreads();
    if (tid == 0) {
        double S = 0.0, SS = 0.0;
        for (int i = 0; i < 8; i++) { S += ws[i]; SS += wss[i]; }
        double m = S / (double)HWSZ;
        double var = SS / (double)HWSZ - m * m;
        double rstd = 1.0 / sqrt(var + 1e-5);
        g_scale[b] = (float)rstd;
        g_shift[b] = (float)(-m * rstd);
    }
}

// ---------------- 2) fused topk + gather + dual MLP (R12 body, 128 threads / 512 blocks) ----------------
// grid (32, NS, QN), block 128, 1 px/thread
__global__ __launch_bounds__(128) void pixel_kernel(const float* __restrict__ corr,
                             const float* __restrict__ w1s, const float* __restrict__ b1s,
                             const float* __restrict__ w2s, const float* __restrict__ b2s,
                             const float* __restrict__ w1c, const float* __restrict__ b1c,
                             const float* __restrict__ w2c, const float* __restrict__ b2c) {
    extern __shared__ float sm[];
    float* sSc = sm;                 // 576
    float* sSh = sSc + 576;          // 576
    float* sW1s = sSh + 576;         // 72*64 transposed [in][out]
    float* sW2s = sW1s + 4608;       // 64*64 [o][j]
    float* sW1c = sW2s + 4096;       // 12*64 transposed
    float* sW2c = sW1c + 768;        // 64*64
    float* sB1s = sW2c + 4096;       // 64
    float* sB2s = sB1s + 64;
    float* sB1c = sB2s + 64;
    float* sB2c = sB1c + 64;
    float* sLvl = sB2c + 64;         // 128*13

    int tid = threadIdx.x;
    int q = blockIdx.z, ns = blockIdx.y;

    for (int i = tid; i < 576; i += 128) {
        int rf = i / 18, cn = i % 18;
        int ch = ((q * RFN + rf) * NSS + ns) * CNN + cn;
        sSc[i] = g_scale[ch];
        sSh[i] = g_shift[ch];
    }
    for (int i = tid; i < 4608; i += 128) sW1s[i] = w1s[(i & 63) * 72 + (i >> 6)];
    for (int i = tid; i < 4096; i += 128) sW2s[i] = w2s[i];
    for (int i = tid; i < 768;  i += 128) sW1c[i] = w1c[(i & 63) * 12 + (i >> 6)];
    for (int i = tid; i < 4096; i += 128) sW2c[i] = w2c[i];
    if (tid < 64) {
        sB1s[tid] = b1s[tid]; sB2s[tid] = b2s[tid];
        sB1c[tid] = b1c[tid]; sB2c[tid] = b2c[tid];
    }
    __syncthreads();

    int hw = blockIdx.x * 128 + tid;
    int cbase = (q * (RFN * NSS * CNN) + ns * CNN) * HWSZ + hw;

    // ---- phase 1: ref score per rfn + top-4 (stable, strict >) ----
    float v0 = -3.4e38f, v1 = v0, v2 = v0, v3 = v0;
    int i0 = 0, i1 = 0, i2 = 0, i3 = 0;
#pragma unroll 2
    for (int rf = 0; rf < RFN; rf++) {
        const float* cp = corr + cbase + rf * (NSS * CNN) * HWSZ;
        float s = 0.f;
#pragma unroll
        for (int cn = 0; cn < CNN; cn++)
            s += fmaf(cp[cn * HWSZ], sSc[rf * 18 + cn], sSh[rf * 18 + cn]);
        if (s > v0)      { v3=v2;i3=i2; v2=v1;i2=i1; v1=v0;i1=i0; v0=s;i0=rf; }
        else if (s > v1) { v3=v2;i3=i2; v2=v1;i2=i1; v1=s;i1=rf; }
        else if (s > v2) { v3=v2;i3=i2; v2=s;i2=rf; }
        else if (s > v3) { v3=s;i3=rf; }
    }
    unsigned packed = (unsigned)i0 | ((unsigned)i1 << 8) | ((unsigned)i2 << 16) | ((unsigned)i3 << 24);

    // ---- phase 2: gather + 72->64 matvec with f32x2 ----
    unsigned long long h2[32];
#pragma unroll
    for (int j = 0; j < 32; j++) h2[j] = pk2b(sB1s[2*j], sB1s[2*j+1]);
#pragma unroll
    for (int i = 0; i < 12; i++) sLvl[tid * 13 + i] = 0.f;

#pragma unroll 1
    for (int k = 0; k < KNN; k++) {
        int rf = (packed >> (k * 8)) & 255;
        const float* cp = corr + cbase + rf * (NSS * CNN) * HWSZ;
        int sb = rf * 18;
#pragma unroll
        for (int cn = 0; cn < CNN; cn++) {
            float xn = fmaf(cp[cn * HWSZ], sSc[sb + cn], sSh[sb + cn]);
            sLvl[tid * 13 + k * 3 + cn / 6] += xn;
            unsigned long long xx = pk2(xn);
            const float4* wp = (const float4*)&sW1s[(k * 18 + cn) * 64];
#pragma unroll
            for (int jj = 0; jj < 16; jj++) {
                F4U2 w; w.f4 = wp[jj];
                h2[2*jj]   = fma2(xx, w.u[0], h2[2*jj]);
                h2[2*jj+1] = fma2(xx, w.u[1], h2[2*jj+1]);
            }
        }
    }
#pragma unroll
    for (int j = 0; j < 32; j++) {
        float2 v = up2(h2[j]);
        h2[j] = pk2b(fmaxf(v.x, 0.f), fmaxf(v.y, 0.f));
    }

    // ---- phase 3: 64->64, write scale-branch features ----
    int obase = ((q * NSS + ns) * 64) * HWSZ + hw;
#pragma unroll 1
    for (int o = 0; o < 64; o += 4) {
        unsigned long long a0 = 0, a1 = 0, a2 = 0, a3 = 0;
        const float4* r0 = (const float4*)&sW2s[(o+0) * 64];
        const float4* r1 = (const float4*)&sW2s[(o+1) * 64];
        const float4* r2 = (const float4*)&sW2s[(o+2) * 64];
        const float4* r3 = (const float4*)&sW2s[(o+3) * 64];
#pragma unroll
        for (int jj = 0; jj < 16; jj++) {
            F4U2 w0, w1, w2, w3;
            w0.f4 = r0[jj]; w1.f4 = r1[jj]; w2.f4 = r2[jj]; w3.f4 = r3[jj];
            a0 = fma2(h2[2*jj], w0.u[0], a0); a0 = fma2(h2[2*jj+1], w0.u[1], a0);
            a1 = fma2(h2[2*jj], w1.u[0], a1); a1 = fma2(h2[2*jj+1], w1.u[1], a1);
            a2 = fma2(h2[2*jj], w2.u[0], a2); a2 = fma2(h2[2*jj+1], w2.u[1], a2);
            a3 = fma2(h2[2*jj], w3.u[0], a3); a3 = fma2(h2[2*jj+1], w3.u[1], a3);
        }
        float2 s0 = up2(a0), s1 = up2(a1), s2 = up2(a2), s3 = up2(a3);
        g_ys[obase + (o+0) * HWSZ] = s0.x + s0.y + sB2s[o+0];
        g_ys[obase + (o+1) * HWSZ] = s1.x + s1.y + sB2s[o+1];
        g_ys[obase + (o+2) * HWSZ] = s2.x + s2.y + sB2s[o+2];
        g_ys[obase + (o+3) * HWSZ] = s3.x + s3.y + sB2s[o+3];
    }

    // ---- phase 4: score branch 12->64 ----
#pragma unroll
    for (int j = 0; j < 32; j++) h2[j] = pk2b(sB1c[2*j], sB1c[2*j+1]);
#pragma unroll 1
    for (int i = 0; i < 12; i++) {
        float xv = sLvl[tid * 13 + i] * (1.0f / 6.0f);
        unsigned long long xx = pk2(xv);
        const float4* wp = (const float4*)&sW1c[i * 64];
#pragma unroll
        for (int jj = 0; jj < 16; jj++) {
            F4U2 w; w.f4 = wp[jj];
            h2[2*jj]   = fma2(xx, w.u[0], h2[2*jj]);
            h2[2*jj+1] = fma2(xx, w.u[1], h2[2*jj+1]);
        }
    }
#pragma unroll
    for (int j = 0; j < 32; j++) {
        float2 v = up2(h2[j]);
        h2[j] = pk2b(fmaxf(v.x, 0.f), fmaxf(v.y, 0.f));
    }

    // ---- phase 5: 64->64, write score-branch features ----
#pragma unroll 1
    for (int o = 0; o < 64; o += 4) {
        unsigned long long a0 = 0, a1 = 0, a2 = 0, a3 = 0;
        const float4* r0 = (const float4*)&sW2c[(o+0) * 64];
        const float4* r1 = (const float4*)&sW2c[(o+1) * 64];
        const float4* r2 = (const float4*)&sW2c[(o+2) * 64];
        const float4* r3 = (const float4*)&sW2c[(o+3) * 64];
#pragma unroll
        for (int jj = 0; jj < 16; jj++) {
            F4U2 w0, w1, w2, w3;
            w0.f4 = r0[jj]; w1.f4 = r1[jj]; w2.f4 = r2[jj]; w3.f4 = r3[jj];
            a0 = fma2(h2[2*jj], w0.u[0], a0); a0 = fma2(h2[2*jj+1], w0.u[1], a0);
            a1 = fma2(h2[2*jj], w1.u[0], a1); a1 = fma2(h2[2*jj+1], w1.u[1], a1);
            a2 = fma2(h2[2*jj], w2.u[0], a2); a2 = fma2(h2[2*jj+1], w2.u[1], a2);
            a3 = fma2(h2[2*jj], w3.u[0], a3); a3 = fma2(h2[2*jj+1], w3.u[1], a3);
        }
        float2 s0 = up2(a0), s1 = up2(a1), s2 = up2(a2), s3 = up2(a3);
        g_yc[obase + (o+0) * HWSZ] = s0.x + s0.y + sB2c[o+0];
        g_yc[obase + (o+1) * HWSZ] = s1.x + s1.y + sB2c[o+1];
        g_yc[obase + (o+2) * HWSZ] = s2.x + s2.y + sB2c[o+2];
        g_yc[obase + (o+3) * HWSZ] = s3.x + s3.y + sB2c[o+3];
    }
}

// ---------------- 3) max over ns, float4 (R12 exact) ----------------
__global__ void maxns_kernel() {
    int idx = (blockIdx.x * 256 + threadIdx.x) << 2;
    int q = idx >> 18;
    int within = idx & ((1 << 18) - 1);
    int base = (q << 20) + within;
    float4 a = *(const float4*)&g_ys[base];
    float4 b = *(const float4*)&g_yc[base];
#pragma unroll
    for (int ns = 1; ns < NSS; ns++) {
        float4 ya = *(const float4*)&g_ys[base + (ns << 18)];
        float4 yb = *(const float4*)&g_yc[base + (ns << 18)];
        a.x = fmaxf(a.x, ya.x); a.y = fmaxf(a.y, ya.y);
        a.z = fmaxf(a.z, ya.z); a.w = fmaxf(a.w, ya.w);
        b.x = fmaxf(b.x, yb.x); b.y = fmaxf(b.y, yb.y);
        b.z = fmaxf(b.z, yb.z); b.w = fmaxf(b.w, yb.w);
    }
    *(float4*)&g_xs[idx] = a;
    *(float4*)&g_xc[idx] = b;
}

// ---------------- 4) conv3x3, batched heads, 8px x 8out threads (R12 exact) ----------------
struct HeadIO {
    const float* in;
    const float* w;
    const float* b;
    float* out;
    int cout;
};

#define CICH 16
#define TROW 20

__global__ __launch_bounds__(128) void conv_mid_kernel(HeadIO a0, HeadIO a1, HeadIO a2) {
    __shared__ __align__(16) float tile[CICH * 18 * TROW];
    __shared__ __align__(16) float wsm[CICH * 288];

    int tid = threadIdx.x;
    int bz = blockIdx.z;
    int head = bz >> 3;
    int rem = bz & 7;
    int q = rem >> 1;
    int co0 = (rem & 1) * 32;
    HeadIO io = (head == 0) ? a0 : ((head == 1) ? a1 : a2);

    int bx = blockIdx.x * 16, by = blockIdx.y * 16;

    int og = tid >> 5;
    int pg = tid & 31;
    int ty = pg >> 1;
    int tx = (pg & 1) << 3;

    unsigned long long acc[8][4];
#pragma unroll
    for (int p = 0; p < 8; p++)
#pragma unroll
        for (int c = 0; c < 4; c++) acc[p][c] = 0ull;

#pragma unroll 1
    for (int cc = 0; cc < 64 / CICH; cc++) {
        if (cc) __syncthreads();
        for (int i = tid; i < CICH * 324; i += 128) {
            int ci = i / 324;
            int r = i - ci * 324;
            int yy = r / 18, xx = r - yy * 18;
            int gy = by + yy - 1, gx = bx + xx - 1;
            float v = 0.f;
            if ((unsigned)gy < 64u && (unsigned)gx < 64u)
                v = io.in[(q * 64 + cc * CICH + ci) * HWSZ + gy * WW + gx];
            tile[ci * (18 * TROW) + yy * TROW + xx] = v;
        }
        for (int i = tid; i < CICH * 288; i += 128) {
            int co = i & 31;
            int tap = (i >> 5) % 9;
            int ci = i / 288;
            wsm[i] = io.w[((co0 + co) * 64 + cc * CICH + ci) * 9 + tap];
        }
        __syncthreads();

#pragma unroll 1
        for (int ci = 0; ci < CICH; ci++) {
            const float* tt = &tile[ci * (18 * TROW) + ty * TROW + tx];
            unsigned long long x2[3][10];
#pragma unroll
            for (int dy = 0; dy < 3; dy++) {
                float4 ra = *(const float4*)&tt[dy * TROW];
                float4 rb = *(const float4*)&tt[dy * TROW + 4];
                float s8 = tt[dy * TROW + 8];
                float s9 = tt[dy * TROW + 9];
                x2[dy][0] = pk2(ra.x); x2[dy][1] = pk2(ra.y);
                x2[dy][2] = pk2(ra.z); x2[dy][3] = pk2(ra.w);
                x2[dy][4] = pk2(rb.x); x2[dy][5] = pk2(rb.y);
                x2[dy][6] = pk2(rb.z); x2[dy][7] = pk2(rb.w);
                x2[dy][8] = pk2(s8);   x2[dy][9] = pk2(s9);
            }
            const float4* wp = (const float4*)&wsm[ci * 288 + og * 8];
#pragma unroll
            for (int tap = 0; tap < 9; tap++) {
                F4U2 wa, wb;
                wa.f4 = wp[tap * 8];
                wb.f4 = wp[tap * 8 + 1];
                int dy = tap / 3, dx = tap % 3;
#pragma unroll
                for (int p = 0; p < 8; p++) {
                    unsigned long long xv = x2[dy][dx + p];
                    acc[p][0] = fma2(xv, wa.u[0], acc[p][0]);
                    acc[p][1] = fma2(xv, wa.u[1], acc[p][1]);
                    acc[p][2] = fma2(xv, wb.u[0], acc[p][2]);
                    acc[p][3] = fma2(xv, wb.u[1], acc[p][3]);
                }
            }
        }
    }

    int ob = (q * 64 + co0 + og * 8) * HWSZ + (by + ty) * WW + bx + tx;
#pragma unroll
    for (int pair = 0; pair < 4; pair++) {
        float blo = io.b[co0 + og * 8 + pair * 2];
        float bhi = io.b[co0 + og * 8 + pair * 2 + 1];
        float2 v[8];
#pragma unroll
        for (int p = 0; p < 8; p++) v[p] = up2(acc[p][pair]);
        float4 lo0 = make_float4(fmaxf(v[0].x + blo, 0.f), fmaxf(v[1].x + blo, 0.f),
                                 fmaxf(v[2].x + blo, 0.f), fmaxf(v[3].x + blo, 0.f));
        float4 lo1 = make_float4(fmaxf(v[4].x + blo, 0.f), fmaxf(v[5].x + blo, 0.f),
                                 fmaxf(v[6].x + blo, 0.f), fmaxf(v[7].x + blo, 0.f));
        float4 hi0 = make_float4(fmaxf(v[0].y + bhi, 0.f), fmaxf(v[1].y + bhi, 0.f),
                                 fmaxf(v[2].y + bhi, 0.f), fmaxf(v[3].y + bhi, 0.f));
        float4 hi1 = make_float4(fmaxf(v[4].y + bhi, 0.f), fmaxf(v[5].y + bhi, 0.f),
                                 fmaxf(v[6].y + bhi, 0.f), fmaxf(v[7].y + bhi, 0.f));
        *(float4*)&io.out[ob + (pair * 2) * HWSZ]     = lo0;
        *(float4*)&io.out[ob + (pair * 2) * HWSZ + 4] = lo1;
        *(float4*)&io.out[ob + (pair * 2 + 1) * HWSZ]     = hi0;
        *(float4*)&io.out[ob + (pair * 2 + 1) * HWSZ + 4] = hi1;
    }
}

__global__ __launch_bounds__(256) void conv_last_kernel(HeadIO a0, HeadIO a1, HeadIO a2) {
    __shared__ float tile[CICH * 342];
    __shared__ float wsm[CICH * 18];

    int tid = threadIdx.x;
    int bz = blockIdx.z;
    int head = bz >> 2;
    int q = bz & 3;
    HeadIO io = (head == 0) ? a0 : ((head == 1) ? a1 : a2);
    int Cout = io.cout;

    int bx = blockIdx.x * 16, by = blockIdx.y * 16;
    int tx = tid & 15, ty = tid >> 4;
    float acc0 = 0.f, acc1 = 0.f;

#pragma unroll 1
    for (int cc = 0; cc < 64 / CICH; cc++) {
        if (cc) __syncthreads();
        for (int i = tid; i < CICH * 324; i += 256) {
            int ci = i / 324;
            int r = i - ci * 324;
            int yy = r / 18, xx = r - yy * 18;
            int gy = by + yy - 1, gx = bx + xx - 1;
            float v = 0.f;
            if ((unsigned)gy < 64u && (unsigned)gx < 64u)
                v = io.in[(q * 64 + cc * CICH + ci) * HWSZ + gy * WW + gx];
            tile[ci * 342 + yy * 19 + xx] = v;
        }
        for (int i = tid; i < CICH * 18; i += 256) {
            int co = i & 1;
            int tap = (i >> 1) % 9;
            int ci = i / 18;
            wsm[i] = (co < Cout) ? io.w[(co * 64 + cc * CICH + ci) * 9 + tap] : 0.f;
        }
        __syncthreads();

#pragma unroll 1
        for (int ci = 0; ci < CICH; ci++) {
            const float* tt = &tile[ci * 342 + ty * 19 + tx];
            const float* wp = &wsm[ci * 18];
#pragma unroll
            for (int tap = 0; tap < 9; tap++) {
                float av = tt[(tap / 3) * 19 + (tap % 3)];
                acc0 = fmaf(av, wp[tap * 2 + 0], acc0);
                acc1 = fmaf(av, wp[tap * 2 + 1], acc1);
            }
        }
    }

    int gy = by + ty, gx = bx + tx;
    io.out[(q * Cout + 0) * HWSZ + gy * WW + gx] = acc0 + io.b[0];
    if (Cout > 1)
        io.out[(q * Cout + 1) * HWSZ + gy * WW + gx] = acc1 + io.b[1];
}

// ---------------- 5) argmax + pos/scl ----------------
__global__ void finalize_kernel(float* out) {
    __shared__ float sv[256];
    __shared__ int si[256];
    int q = blockIdx.x, tid = threadIdx.x;
    const float* sc = out + OFF_SCORES + q * HWSZ;
    float bv = -3.4e38f;
    int bi = 0;
    for (int i = tid; i < HWSZ; i += 256) {
        float v = sc[i];
        if (v > bv) { bv = v; bi = i; }
    }
    sv[tid] = bv; si[tid] = bi;
    __syncthreads();
    for (int s = 128; s > 0; s >>= 1) {
        if (tid < s) {
            if (sv[tid + s] > sv[tid] || (sv[tid + s] == sv[tid] && si[tid + s] < si[tid])) {
                sv[tid] = sv[tid + s];
                si[tid] = si[tid + s];
            }
        }
        __syncthreads();
    }
    if (tid == 0) {
        int idx = si[0];
        int sy = idx >> 6, sx = idx & 63;
        float offx = out[OFF_OFFS + (q * 2 + 0) * HWSZ + idx];
        float offy = out[OFF_OFFS + (q * 2 + 1) * HWSZ + idx];
        float sclv = out[OFF_SCALES + q * HWSZ + idx];
        out[OFF_POS + q * 2 + 0] = ((float)sx + offx + 0.5f) * 8.0f - 0.5f;
        out[OFF_POS + q * 2 + 1] = ((float)sy + offy + 0.5f) * 8.0f - 0.5f;
        out[OFF_SCL + q] = exp2f(sclv);
    }
}

// ---------------- launch ----------------
extern "C" void kernel_launch(void* const* d_in, const int* in_sizes, int n_in,
                              void* d_out, int out_size) {
    const float* corr = (const float*)d_in[0];
    float* out = (float*)d_out;

    float *xs_p, *xc_p, *t1_p, *t2_p;
    cudaGetSymbolAddress((void**)&xs_p, g_xs);
    cudaGetSymbolAddress((void**)&xc_p, g_xc);
    cudaGetSymbolAddress((void**)&t1_p, g_t1);
    cudaGetSymbolAddress((void**)&t2_p, g_t2);
    const int HSZ = QN * 64 * HWSZ;

    const int PIX_SMEM = (576*2 + 4608 + 4096 + 768 + 4096 + 256 + 128*13) * 4;
    cudaFuncSetAttribute(pixel_kernel, cudaFuncAttributeMaxDynamicSharedMemorySize, PIX_SMEM);

    stats_kernel<<<QN * RFN * NSS * CNN, 256>>>(corr);

    pixel_kernel<<<dim3(32, NSS, QN), 128, PIX_SMEM>>>(
        corr, (const float*)d_in[1], (const float*)d_in[2],
        (const float*)d_in[3], (const float*)d_in[4],
        (const float*)d_in[5], (const float*)d_in[6],
        (const float*)d_in[7], (const float*)d_in[8]);

    maxns_kernel<<<1024, 256>>>();

    {
        HeadIO h0 = { xs_p, (const float*)d_in[9],  (const float*)d_in[10], t1_p + 0*HSZ, 64 };
        HeadIO h1 = { xc_p, (const float*)d_in[15], (const float*)d_in[16], t1_p + 1*HSZ, 64 };
        HeadIO h2 = { xc_p, (const float*)d_in[21], (const float*)d_in[22], t1_p + 2*HSZ, 64 };
        conv_mid_kernel<<<dim3(4, 4, 24), 128>>>(h0, h1, h2);
    }
    {
        HeadIO h0 = { t1_p + 0*HSZ, (const float*)d_in[11], (const float*)d_in[12], t2_p + 0*HSZ, 64 };
        HeadIO h1 = { t1_p + 1*HSZ, (const float*)d_in[17], (const float*)d_in[18], t2_p + 1*HSZ, 64 };
        HeadIO h2 = { t1_p + 2*HSZ, (const float*)d_in[23], (const float*)d_in[24], t2_p + 2*HSZ, 64 };
        conv_mid_kernel<<<dim3(4, 4, 24), 128>>>(h0, h1, h2);
    }
    {
        HeadIO h0 = { t2_p + 0*HSZ, (const float*)d_in[13], (const float*)d_in[14], out + OFF_SCALES, 1 };
        HeadIO h1 = { t2_p + 1*HSZ, (const float*)d_in[19], (const float*)d_in[20], out + OFF_OFFS, 2 };
        HeadIO h2 = { t2_p + 2*HSZ, (const float*)d_in[25], (const float*)d_in[26], out + OFF_SCORES, 1 };
        conv_last_kernel<<<dim3(4, 4, 12), 256>>>(h0, h1, h2);
    }

    finalize_kernel<<<QN, 256>>>(out);
}

// round 16
// speedup vs baseline: 1.1342x; 1.1342x over previous
#include <cuda_runtime.h>
#include <math.h>

#define QN 4
#define RFN 32
#define NSS 4
#define CNN 18
#define HH 64
#define WW 64
#define HWSZ 4096
#define KNN 4

#define OFF_POS 0
#define OFF_SCL 8
#define OFF_SCORES 12
#define OFF_SCALES (12 + 16384)
#define OFF_OFFS (12 + 32768)

// ---------------- f32x2 helpers ----------------
__device__ __forceinline__ unsigned long long pk2(float x) {
    unsigned long long r;
    asm("mov.b64 %0, {%1, %1};" : "=l"(r) : "f"(x));
    return r;
}
__device__ __forceinline__ unsigned long long pk2b(float a, float b) {
    unsigned long long r;
    asm("mov.b64 %0, {%1, %2};" : "=l"(r) : "f"(a), "f"(b));
    return r;
}
__device__ __forceinline__ unsigned long long fma2(unsigned long long a, unsigned long long b,
                                                   unsigned long long c) {
    unsigned long long d;
    asm("fma.rn.f32x2 %0, %1, %2, %3;" : "=l"(d) : "l"(a), "l"(b), "l"(c));
    return d;
}
__device__ __forceinline__ float2 up2(unsigned long long v) {
    float lo, hi;
    asm("mov.b64 {%0, %1}, %2;" : "=f"(lo), "=f"(hi) : "l"(v));
    return make_float2(lo, hi);
}
union F4U2 { float4 f4; unsigned long long u[2]; };

// ---------------- device scratch ----------------
__device__ float g_scale[QN * RFN * NSS * CNN];
__device__ float g_shift[QN * RFN * NSS * CNN];
__device__ float g_ys[QN * NSS * 64 * HWSZ];
__device__ float g_yc[QN * NSS * 64 * HWSZ];
__device__ float g_xs[QN * 64 * HWSZ];
__device__ float g_xc[QN * 64 * HWSZ];
__device__ float g_t1[3 * QN * 64 * HWSZ];
__device__ float g_t2[3 * QN * 64 * HWSZ];

// ---------------- 1) per-channel mean / rstd ----------------
__global__ void stats_kernel(const float* __restrict__ corr) {
    int b = blockIdx.x;
    int tid = threadIdx.x;
    const float* p = corr + (size_t)b * HWSZ;
    double s = 0.0, ss = 0.0;
    for (int i = tid; i < HWSZ; i += 256) {
        float v = p[i];
        s += v;
        ss += (double)v * v;
    }
    for (int o = 16; o > 0; o >>= 1) {
        s += __shfl_down_sync(0xffffffffu, s, o);
        ss += __shfl_down_sync(0xffffffffu, ss, o);
    }
    __shared__ double ws[8], wss[8];
    if ((tid & 31) == 0) { ws[tid >> 5] = s; wss[tid >> 5] = ss; }
    __syncthreads();
    if (tid == 0) {
        double S = 0.0, SS = 0.0;
        for (int i = 0; i < 8; i++) { S += ws[i]; SS += wss[i]; }
        double m = S / (double)HWSZ;
        double var = SS / (double)HWSZ - m * m;
        double rstd = 1.0 / sqrt(var + 1e-5);
        g_scale[b] = (float)rstd;
        g_shift[b] = (float)(-m * rstd);
    }
}

// ---------------- 2) fused topk + gather + dual MLP (R12 + unroll-2 out loops) ----------------
// grid (16, NS, QN), block 256
__global__ void pixel_kernel(const float* __restrict__ corr,
                             const float* __restrict__ w1s, const float* __restrict__ b1s,
                             const float* __restrict__ w2s, const float* __restrict__ b2s,
                             const float* __restrict__ w1c, const float* __restrict__ b1c,
                             const float* __restrict__ w2c, const float* __restrict__ b2c) {
    extern __shared__ float sm[];
    float* sSc = sm;                 // 576
    float* sSh = sSc + 576;          // 576
    float* sW1s = sSh + 576;         // 72*64 transposed [in][out]
    float* sW2s = sW1s + 4608;       // 64*64 [o][j]
    float* sW1c = sW2s + 4096;       // 12*64 transposed
    float* sW2c = sW1c + 768;        // 64*64
    float* sB1s = sW2c + 4096;       // 64
    float* sB2s = sB1s + 64;
    float* sB1c = sB2s + 64;
    float* sB2c = sB1c + 64;
    float* sLvl = sB2c + 64;         // 256*13

    int tid = threadIdx.x;
    int q = blockIdx.z, ns = blockIdx.y;

    for (int i = tid; i < 576; i += 256) {
        int rf = i / 18, cn = i % 18;
        int ch = ((q * RFN + rf) * NSS + ns) * CNN + cn;
        sSc[i] = g_scale[ch];
        sSh[i] = g_shift[ch];
    }
    for (int i = tid; i < 4608; i += 256) sW1s[i] = w1s[(i & 63) * 72 + (i >> 6)];
    for (int i = tid; i < 4096; i += 256) sW2s[i] = w2s[i];
    for (int i = tid; i < 768;  i += 256) sW1c[i] = w1c[(i & 63) * 12 + (i >> 6)];
    for (int i = tid; i < 4096; i += 256) sW2c[i] = w2c[i];
    if (tid < 64) {
        sB1s[tid] = b1s[tid]; sB2s[tid] = b2s[tid];
        sB1c[tid] = b1c[tid]; sB2c[tid] = b2c[tid];
    }
    __syncthreads();

    int hw = blockIdx.x * 256 + tid;
    int cbase = (q * (RFN * NSS * CNN) + ns * CNN) * HWSZ + hw;

    // ---- phase 1: ref score per rfn + top-4 (stable, strict >) ----
    float v0 = -3.4e38f, v1 = v0, v2 = v0, v3 = v0;
    int i0 = 0, i1 = 0, i2 = 0, i3 = 0;
#pragma unroll 2
    for (int rf = 0; rf < RFN; rf++) {
        const float* cp = corr + cbase + rf * (NSS * CNN) * HWSZ;
        float s = 0.f;
#pragma unroll
        for (int cn = 0; cn < CNN; cn++)
            s += fmaf(cp[cn * HWSZ], sSc[rf * 18 + cn], sSh[rf * 18 + cn]);
        if (s > v0)      { v3=v2;i3=i2; v2=v1;i2=i1; v1=v0;i1=i0; v0=s;i0=rf; }
        else if (s > v1) { v3=v2;i3=i2; v2=v1;i2=i1; v1=s;i1=rf; }
        else if (s > v2) { v3=v2;i3=i2; v2=s;i2=rf; }
        else if (s > v3) { v3=s;i3=rf; }
    }
    unsigned packed = (unsigned)i0 | ((unsigned)i1 << 8) | ((unsigned)i2 << 16) | ((unsigned)i3 << 24);

    // ---- phase 2: gather + 72->64 matvec with f32x2 ----
    unsigned long long h2[32];
#pragma unroll
    for (int j = 0; j < 32; j++) h2[j] = pk2b(sB1s[2*j], sB1s[2*j+1]);
#pragma unroll
    for (int i = 0; i < 12; i++) sLvl[tid * 13 + i] = 0.f;

#pragma unroll 1
    for (int k = 0; k < KNN; k++) {
        int rf = (packed >> (k * 8)) & 255;
        const float* cp = corr + cbase + rf * (NSS * CNN) * HWSZ;
        int sb = rf * 18;
#pragma unroll
        for (int cn = 0; cn < CNN; cn++) {
            float xn = fmaf(cp[cn * HWSZ], sSc[sb + cn], sSh[sb + cn]);
            sLvl[tid * 13 + k * 3 + cn / 6] += xn;
            unsigned long long xx = pk2(xn);
            const float4* wp = (const float4*)&sW1s[(k * 18 + cn) * 64];
#pragma unroll
            for (int jj = 0; jj < 16; jj++) {
                F4U2 w; w.f4 = wp[jj];
                h2[2*jj]   = fma2(xx, w.u[0], h2[2*jj]);
                h2[2*jj+1] = fma2(xx, w.u[1], h2[2*jj+1]);
            }
        }
    }
#pragma unroll
    for (int j = 0; j < 32; j++) {
        float2 v = up2(h2[j]);
        h2[j] = pk2b(fmaxf(v.x, 0.f), fmaxf(v.y, 0.f));
    }

    // ---- phase 3: 64->64, write scale-branch features ----
    int obase = ((q * NSS + ns) * 64) * HWSZ + hw;
#pragma unroll 2
    for (int o = 0; o < 64; o += 4) {
        unsigned long long a0 = 0, a1 = 0, a2 = 0, a3 = 0;
        const float4* r0 = (const float4*)&sW2s[(o+0) * 64];
        const float4* r1 = (const float4*)&sW2s[(o+1) * 64];
        const float4* r2 = (const float4*)&sW2s[(o+2) * 64];
        const float4* r3 = (const float4*)&sW2s[(o+3) * 64];
#pragma unroll
        for (int jj = 0; jj < 16; jj++) {
            F4U2 w0, w1, w2, w3;
            w0.f4 = r0[jj]; w1.f4 = r1[jj]; w2.f4 = r2[jj]; w3.f4 = r3[jj];
            a0 = fma2(h2[2*jj], w0.u[0], a0); a0 = fma2(h2[2*jj+1], w0.u[1], a0);
            a1 = fma2(h2[2*jj], w1.u[0], a1); a1 = fma2(h2[2*jj+1], w1.u[1], a1);
            a2 = fma2(h2[2*jj], w2.u[0], a2); a2 = fma2(h2[2*jj+1], w2.u[1], a2);
            a3 = fma2(h2[2*jj], w3.u[0], a3); a3 = fma2(h2[2*jj+1], w3.u[1], a3);
        }
        float2 s0 = up2(a0), s1 = up2(a1), s2 = up2(a2), s3 = up2(a3);
        g_ys[obase + (o+0) * HWSZ] = s0.x + s0.y + sB2s[o+0];
        g_ys[obase + (o+1) * HWSZ] = s1.x + s1.y + sB2s[o+1];
        g_ys[obase + (o+2) * HWSZ] = s2.x + s2.y + sB2s[o+2];
        g_ys[obase + (o+3) * HWSZ] = s3.x + s3.y + sB2s[o+3];
    }

    // ---- phase 4: score branch 12->64 ----
#pragma unroll
    for (int j = 0; j < 32; j++) h2[j] = pk2b(sB1c[2*j], sB1c[2*j+1]);
#pragma unroll 1
    for (int i = 0; i < 12; i++) {
        float xv = sLvl[tid * 13 + i] * (1.0f / 6.0f);
        unsigned long long xx = pk2(xv);
        const float4* wp = (const float4*)&sW1c[i * 64];
#pragma unroll
        for (int jj = 0; jj < 16; jj++) {
            F4U2 w; w.f4 = wp[jj];
            h2[2*jj]   = fma2(xx, w.u[0], h2[2*jj]);
            h2[2*jj+1] = fma2(xx, w.u[1], h2[2*jj+1]);
        }
    }
#pragma unroll
    for (int j = 0; j < 32; j++) {
        float2 v = up2(h2[j]);
        h2[j] = pk2b(fmaxf(v.x, 0.f), fmaxf(v.y, 0.f));
    }

    // ---- phase 5: 64->64, write score-branch features ----
#pragma unroll 2
    for (int o = 0; o < 64; o += 4) {
        unsigned long long a0 = 0, a1 = 0, a2 = 0, a3 = 0;
        const float4* r0 = (const float4*)&sW2c[(o+0) * 64];
        const float4* r1 = (const float4*)&sW2c[(o+1) * 64];
        const float4* r2 = (const float4*)&sW2c[(o+2) * 64];
        const float4* r3 = (const float4*)&sW2c[(o+3) * 64];
#pragma unroll
        for (int jj = 0; jj < 16; jj++) {
            F4U2 w0, w1, w2, w3;
            w0.f4 = r0[jj]; w1.f4 = r1[jj]; w2.f4 = r2[jj]; w3.f4 = r3[jj];
            a0 = fma2(h2[2*jj], w0.u[0], a0); a0 = fma2(h2[2*jj+1], w0.u[1], a0);
            a1 = fma2(h2[2*jj], w1.u[0], a1); a1 = fma2(h2[2*jj+1], w1.u[1], a1);
            a2 = fma2(h2[2*jj], w2.u[0], a2); a2 = fma2(h2[2*jj+1], w2.u[1], a2);
            a3 = fma2(h2[2*jj], w3.u[0], a3); a3 = fma2(h2[2*jj+1], w3.u[1], a3);
        }
        float2 s0 = up2(a0), s1 = up2(a1), s2 = up2(a2), s3 = up2(a3);
        g_yc[obase + (o+0) * HWSZ] = s0.x + s0.y + sB2c[o+0];
        g_yc[obase + (o+1) * HWSZ] = s1.x + s1.y + sB2c[o+1];
        g_yc[obase + (o+2) * HWSZ] = s2.x + s2.y + sB2c[o+2];
        g_yc[obase + (o+3) * HWSZ] = s3.x + s3.y + sB2c[o+3];
    }
}

// ---------------- 3) max over ns, float4 (R12 exact) ----------------
__global__ void maxns_kernel() {
    int idx = (blockIdx.x * 256 + threadIdx.x) << 2;
    int q = idx >> 18;
    int within = idx & ((1 << 18) - 1);
    int base = (q << 20) + within;
    float4 a = *(const float4*)&g_ys[base];
    float4 b = *(const float4*)&g_yc[base];
#pragma unroll
    for (int ns = 1; ns < NSS; ns++) {
        float4 ya = *(const float4*)&g_ys[base + (ns << 18)];
        float4 yb = *(const float4*)&g_yc[base + (ns << 18)];
        a.x = fmaxf(a.x, ya.x); a.y = fmaxf(a.y, ya.y);
        a.z = fmaxf(a.z, ya.z); a.w = fmaxf(a.w, ya.w);
        b.x = fmaxf(b.x, yb.x); b.y = fmaxf(b.y, yb.y);
        b.z = fmaxf(b.z, yb.z); b.w = fmaxf(b.w, yb.w);
    }
    *(float4*)&g_xs[idx] = a;
    *(float4*)&g_xc[idx] = b;
}

// ---------------- 4) conv3x3, batched heads, 8px x 8out threads (R12 exact) ----------------
struct HeadIO {
    const float* in;
    const float* w;
    const float* b;
    float* out;
    int cout;
};

#define CICH 16
#define TROW 20

__global__ __launch_bounds__(128) void conv_mid_kernel(HeadIO a0, HeadIO a1, HeadIO a2) {
    __shared__ __align__(16) float tile[CICH * 18 * TROW];
    __shared__ __align__(16) float wsm[CICH * 288];

    int tid = threadIdx.x;
    int bz = blockIdx.z;
    int head = bz >> 3;
    int rem = bz & 7;
    int q = rem >> 1;
    int co0 = (rem & 1) * 32;
    HeadIO io = (head == 0) ? a0 : ((head == 1) ? a1 : a2);

    int bx = blockIdx.x * 16, by = blockIdx.y * 16;

    int og = tid >> 5;
    int pg = tid & 31;
    int ty = pg >> 1;
    int tx = (pg & 1) << 3;

    unsigned long long acc[8][4];
#pragma unroll
    for (int p = 0; p < 8; p++)
#pragma unroll
        for (int c = 0; c < 4; c++) acc[p][c] = 0ull;

#pragma unroll 1
    for (int cc = 0; cc < 64 / CICH; cc++) {
        if (cc) __syncthreads();
        for (int i = tid; i < CICH * 324; i += 128) {
            int ci = i / 324;
            int r = i - ci * 324;
            int yy = r / 18, xx = r - yy * 18;
            int gy = by + yy - 1, gx = bx + xx - 1;
            float v = 0.f;
            if ((unsigned)gy < 64u && (unsigned)gx < 64u)
                v = io.in[(q * 64 + cc * CICH + ci) * HWSZ + gy * WW + gx];
            tile[ci * (18 * TROW) + yy * TROW + xx] = v;
        }
        for (int i = tid; i < CICH * 288; i += 128) {
            int co = i & 31;
            int tap = (i >> 5) % 9;
            int ci = i / 288;
            wsm[i] = io.w[((co0 + co) * 64 + cc * CICH + ci) * 9 + tap];
        }
        __syncthreads();

#pragma unroll 1
        for (int ci = 0; ci < CICH; ci++) {
            const float* tt = &tile[ci * (18 * TROW) + ty * TROW + tx];
            unsigned long long x2[3][10];
#pragma unroll
            for (int dy = 0; dy < 3; dy++) {
                float4 ra = *(const float4*)&tt[dy * TROW];
                float4 rb = *(const float4*)&tt[dy * TROW + 4];
                float s8 = tt[dy * TROW + 8];
                float s9 = tt[dy * TROW + 9];
                x2[dy][0] = pk2(ra.x); x2[dy][1] = pk2(ra.y);
                x2[dy][2] = pk2(ra.z); x2[dy][3] = pk2(ra.w);
                x2[dy][4] = pk2(rb.x); x2[dy][5] = pk2(rb.y);
                x2[dy][6] = pk2(rb.z); x2[dy][7] = pk2(rb.w);
                x2[dy][8] = pk2(s8);   x2[dy][9] = pk2(s9);
            }
            const float4* wp = (const float4*)&wsm[ci * 288 + og * 8];
#pragma unroll
            for (int tap = 0; tap < 9; tap++) {
                F4U2 wa, wb;
                wa.f4 = wp[tap * 8];
                wb.f4 = wp[tap * 8 + 1];
                int dy = tap / 3, dx = tap % 3;
#pragma unroll
                for (int p = 0; p < 8; p++) {
                    unsigned long long xv = x2[dy][dx + p];
                    acc[p][0] = fma2(xv, wa.u[0], acc[p][0]);
                    acc[p][1] = fma2(xv, wa.u[1], acc[p][1]);
                    acc[p][2] = fma2(xv, wb.u[0], acc[p][2]);
                    acc[p][3] = fma2(xv, wb.u[1], acc[p][3]);
                }
            }
        }
    }

    int ob = (q * 64 + co0 + og * 8) * HWSZ + (by + ty) * WW + bx + tx;
#pragma unroll
    for (int pair = 0; pair < 4; pair++) {
        float blo = io.b[co0 + og * 8 + pair * 2];
        float bhi = io.b[co0 + og * 8 + pair * 2 + 1];
        float2 v[8];
#pragma unroll
        for (int p = 0; p < 8; p++) v[p] = up2(acc[p][pair]);
        float4 lo0 = make_float4(fmaxf(v[0].x + blo, 0.f), fmaxf(v[1].x + blo, 0.f),
                                 fmaxf(v[2].x + blo, 0.f), fmaxf(v[3].x + blo, 0.f));
        float4 lo1 = make_float4(fmaxf(v[4].x + blo, 0.f), fmaxf(v[5].x + blo, 0.f),
                                 fmaxf(v[6].x + blo, 0.f), fmaxf(v[7].x + blo, 0.f));
        float4 hi0 = make_float4(fmaxf(v[0].y + bhi, 0.f), fmaxf(v[1].y + bhi, 0.f),
                                 fmaxf(v[2].y + bhi, 0.f), fmaxf(v[3].y + bhi, 0.f));
        float4 hi1 = make_float4(fmaxf(v[4].y + bhi, 0.f), fmaxf(v[5].y + bhi, 0.f),
                                 fmaxf(v[6].y + bhi, 0.f), fmaxf(v[7].y + bhi, 0.f));
        *(float4*)&io.out[ob + (pair * 2) * HWSZ]     = lo0;
        *(float4*)&io.out[ob + (pair * 2) * HWSZ + 4] = lo1;
        *(float4*)&io.out[ob + (pair * 2 + 1) * HWSZ]     = hi0;
        *(float4*)&io.out[ob + (pair * 2 + 1) * HWSZ + 4] = hi1;
    }
}

__global__ __launch_bounds__(256) void conv_last_kernel(HeadIO a0, HeadIO a1, HeadIO a2) {
    __shared__ float tile[CICH * 342];
    __shared__ float wsm[CICH * 18];

    int tid = threadIdx.x;
    int bz = blockIdx.z;
    int head = bz >> 2;
    int q = bz & 3;
    HeadIO io = (head == 0) ? a0 : ((head == 1) ? a1 : a2);
    int Cout = io.cout;

    int bx = blockIdx.x * 16, by = blockIdx.y * 16;
    int tx = tid & 15, ty = tid >> 4;
    float acc0 = 0.f, acc1 = 0.f;

#pragma unroll 1
    for (int cc = 0; cc < 64 / CICH; cc++) {
        if (cc) __syncthreads();
        for (int i = tid; i < CICH * 324; i += 256) {
            int ci = i / 324;
            int r = i - ci * 324;
            int yy = r / 18, xx = r - yy * 18;
            int gy = by + yy - 1, gx = bx + xx - 1;
            float v = 0.f;
            if ((unsigned)gy < 64u && (unsigned)gx < 64u)
                v = io.in[(q * 64 + cc * CICH + ci) * HWSZ + gy * WW + gx];
            tile[ci * 342 + yy * 19 + xx] = v;
        }
        for (int i = tid; i < CICH * 18; i += 256) {
            int co = i & 1;
            int tap = (i >> 1) % 9;
            int ci = i / 18;
            wsm[i] = (co < Cout) ? io.w[(co * 64 + cc * CICH + ci) * 9 + tap] : 0.f;
        }
        __syncthreads();

#pragma unroll 1
        for (int ci = 0; ci < CICH; ci++) {
            const float* tt = &tile[ci * 342 + ty * 19 + tx];
            const float* wp = &wsm[ci * 18];
#pragma unroll
            for (int tap = 0; tap < 9; tap++) {
                float av = tt[(tap / 3) * 19 + (tap % 3)];
                acc0 = fmaf(av, wp[tap * 2 + 0], acc0);
                acc1 = fmaf(av, wp[tap * 2 + 1], acc1);
            }
        }
    }

    int gy = by + ty, gx = bx + tx;
    io.out[(q * Cout + 0) * HWSZ + gy * WW + gx] = acc0 + io.b[0];
    if (Cout > 1)
        io.out[(q * Cout + 1) * HWSZ + gy * WW + gx] = acc1 + io.b[1];
}

// ---------------- 5) argmax + pos/scl ----------------
__global__ void finalize_kernel(float* out) {
    __shared__ float sv[256];
    __shared__ int si[256];
    int q = blockIdx.x, tid = threadIdx.x;
    const float* sc = out + OFF_SCORES + q * HWSZ;
    float bv = -3.4e38f;
    int bi = 0;
    for (int i = tid; i < HWSZ; i += 256) {
        float v = sc[i];
        if (v > bv) { bv = v; bi = i; }
    }
    sv[tid] = bv; si[tid] = bi;
    __syncthreads();
    for (int s = 128; s > 0; s >>= 1) {
        if (tid < s) {
            if (sv[tid + s] > sv[tid] || (sv[tid + s] == sv[tid] && si[tid + s] < si[tid])) {
                sv[tid] = sv[tid + s];
                si[tid] = si[tid + s];
            }
        }
        __syncthreads();
    }
    if (tid == 0) {
        int idx = si[0];
        int sy = idx >> 6, sx = idx & 63;
        float offx = out[OFF_OFFS + (q * 2 + 0) * HWSZ + idx];
        float offy = out[OFF_OFFS + (q * 2 + 1) * HWSZ + idx];
        float sclv = out[OFF_SCALES + q * HWSZ + idx];
        out[OFF_POS + q * 2 + 0] = ((float)sx + offx + 0.5f) * 8.0f - 0.5f;
        out[OFF_POS + q * 2 + 1] = ((float)sy + offy + 0.5f) * 8.0f - 0.5f;
        out[OFF_SCL + q] = exp2f(sclv);
    }
}

// ---------------- launch ----------------
extern "C" void kernel_launch(void* const* d_in, const int* in_sizes, int n_in,
                              void* d_out, int out_size) {
    const float* corr = (const float*)d_in[0];
    float* out = (float*)d_out;

    float *xs_p, *xc_p, *t1_p, *t2_p;
    cudaGetSymbolAddress((void**)&xs_p, g_xs);
    cudaGetSymbolAddress((void**)&xc_p, g_xc);
    cudaGetSymbolAddress((void**)&t1_p, g_t1);
    cudaGetSymbolAddress((void**)&t2_p, g_t2);
    const int HSZ = QN * 64 * HWSZ;

    const int PIX_SMEM = (576*2 + 4608 + 4096 + 768 + 4096 + 256 + 256*13) * 4;
    cudaFuncSetAttribute(pixel_kernel, cudaFuncAttributeMaxDynamicSharedMemorySize, PIX_SMEM);

    stats_kernel<<<QN * RFN * NSS * CNN, 256>>>(corr);

    pixel_kernel<<<dim3(16, NSS, QN), 256, PIX_SMEM>>>(
        corr, (const float*)d_in[1], (const float*)d_in[2],
        (const float*)d_in[3], (const float*)d_in[4],
        (const float*)d_in[5], (const float*)d_in[6],
        (const float*)d_in[7], (const float*)d_in[8]);

    maxns_kernel<<<1024, 256>>>();

    {
        HeadIO h0 = { xs_p, (const float*)d_in[9],  (const float*)d_in[10], t1_p + 0*HSZ, 64 };
        HeadIO h1 = { xc_p, (const float*)d_in[15], (const float*)d_in[16], t1_p + 1*HSZ, 64 };
        HeadIO h2 = { xc_p, (const float*)d_in[21], (const float*)d_in[22], t1_p + 2*HSZ, 64 };
        conv_mid_kernel<<<dim3(4, 4, 24), 128>>>(h0, h1, h2);
    }
    {
        HeadIO h0 = { t1_p + 0*HSZ, (const float*)d_in[11], (const float*)d_in[12], t2_p + 0*HSZ, 64 };
        HeadIO h1 = { t1_p + 1*HSZ, (const float*)d_in[17], (const float*)d_in[18], t2_p + 1*HSZ, 64 };
        HeadIO h2 = { t1_p + 2*HSZ, (const float*)d_in[23], (const float*)d_in[24], t2_p + 2*HSZ, 64 };
        conv_mid_kernel<<<dim3(4, 4, 24), 128>>>(h0, h1, h2);
    }
    {
        HeadIO h0 = { t2_p + 0*HSZ, (const float*)d_in[13], (const float*)d_in[14], out + OFF_SCALES, 1 };
        HeadIO h1 = { t2_p + 1*HSZ, (const float*)d_in[19], (const float*)d_in[20], out + OFF_OFFS, 2 };
        HeadIO h2 = { t2_p + 2*HSZ, (const float*)d_in[25], (const float*)d_in[26], out + OFF_SCORES, 1 };
        conv_last_kernel<<<dim3(4, 4, 12), 256>>>(h0, h1, h2);
    }

    finalize_kernel<<<QN, 256>>>(out);
}

// round 17
// speedup vs baseline: 1.8390x; 1.6214x over previous
#include <cuda_runtime.h>
#include <math.h>

#define QN 4
#define RFN 32
#define NSS 4
#define CNN 18
#define HH 64
#define WW 64
#define HWSZ 4096
#define KNN 4

#define OFF_POS 0
#define OFF_SCL 8
#define OFF_SCORES 12
#define OFF_SCALES (12 + 16384)
#define OFF_OFFS (12 + 32768)

// ---------------- f32x2 helpers ----------------
__device__ __forceinline__ unsigned long long pk2(float x) {
    unsigned long long r;
    asm("mov.b64 %0, {%1, %1};" : "=l"(r) : "f"(x));
    return r;
}
__device__ __forceinline__ unsigned long long pk2b(float a, float b) {
    unsigned long long r;
    asm("mov.b64 %0, {%1, %2};" : "=l"(r) : "f"(a), "f"(b));
    return r;
}
__device__ __forceinline__ unsigned long long fma2(unsigned long long a, unsigned long long b,
                                                   unsigned long long c) {
    unsigned long long d;
    asm("fma.rn.f32x2 %0, %1, %2, %3;" : "=l"(d) : "l"(a), "l"(b), "l"(c));
    return d;
}
__device__ __forceinline__ float2 up2(unsigned long long v) {
    float lo, hi;
    asm("mov.b64 {%0, %1}, %2;" : "=f"(lo), "=f"(hi) : "l"(v));
    return make_float2(lo, hi);
}
union F4U2 { float4 f4; unsigned long long u[2]; };

// ---------------- device scratch ----------------
__device__ float g_scale[QN * RFN * NSS * CNN];
__device__ float g_shift[QN * RFN * NSS * CNN];
__device__ float g_ys[QN * NSS * 64 * HWSZ];
__device__ float g_yc[QN * NSS * 64 * HWSZ];
__device__ float g_xs[QN * 64 * HWSZ];
__device__ float g_xc[QN * 64 * HWSZ];
__device__ float g_t1[3 * QN * 64 * HWSZ];
__device__ float g_t2[3 * QN * 64 * HWSZ];

// ---------------- 1) per-channel mean / rstd (fp32, float4, wide partials) ----------------
__global__ void stats_kernel(const float* __restrict__ corr) {
    int b = blockIdx.x;
    int tid = threadIdx.x;
    const float4* p = (const float4*)(corr + (size_t)b * HWSZ);
    float4 s4 = make_float4(0.f, 0.f, 0.f, 0.f);
    float4 q4 = make_float4(0.f, 0.f, 0.f, 0.f);
#pragma unroll
    for (int it = 0; it < 4; it++) {
        float4 v = p[tid + it * 256];
        s4.x += v.x; s4.y += v.y; s4.z += v.z; s4.w += v.w;
        q4.x = fmaf(v.x, v.x, q4.x); q4.y = fmaf(v.y, v.y, q4.y);
        q4.z = fmaf(v.z, v.z, q4.z); q4.w = fmaf(v.w, v.w, q4.w);
    }
    float s = (s4.x + s4.y) + (s4.z + s4.w);
    float ss = (q4.x + q4.y) + (q4.z + q4.w);
    for (int o = 16; o > 0; o >>= 1) {
        s += __shfl_down_sync(0xffffffffu, s, o);
        ss += __shfl_down_sync(0xffffffffu, ss, o);
    }
    __shared__ float ws[8], wss[8];
    if ((tid & 31) == 0) { ws[tid >> 5] = s; wss[tid >> 5] = ss; }
    __syncthreads();
    if (tid == 0) {
        float S = 0.f, SS = 0.f;
#pragma unroll
        for (int i = 0; i < 8; i++) { S += ws[i]; SS += wss[i]; }
        float m = S * (1.0f / HWSZ);
        float var = fmaf(-m, m, SS * (1.0f / HWSZ));
        float rstd = rsqrtf(var + 1e-5f);
        // one Newton step for full fp32 rsqrt accuracy
        float e = var + 1e-5f;
        rstd = rstd * (1.5f - 0.5f * e * rstd * rstd);
        g_scale[b] = rstd;
        g_shift[b] = -m * rstd;
    }
}

// ---------------- 2) fused topk + gather + dual MLP (R16 exact) ----------------
// grid (16, NS, QN), block 256
__global__ void pixel_kernel(const float* __restrict__ corr,
                             const float* __restrict__ w1s, const float* __restrict__ b1s,
                             const float* __restrict__ w2s, const float* __restrict__ b2s,
                             const float* __restrict__ w1c, const float* __restrict__ b1c,
                             const float* __restrict__ w2c, const float* __restrict__ b2c) {
    extern __shared__ float sm[];
    float* sSc = sm;                 // 576
    float* sSh = sSc + 576;          // 576
    float* sW1s = sSh + 576;         // 72*64 transposed [in][out]
    float* sW2s = sW1s + 4608;       // 64*64 [o][j]
    float* sW1c = sW2s + 4096;       // 12*64 transposed
    float* sW2c = sW1c + 768;        // 64*64
    float* sB1s = sW2c + 4096;       // 64
    float* sB2s = sB1s + 64;
    float* sB1c = sB2s + 64;
    float* sB2c = sB1c + 64;
    float* sLvl = sB2c + 64;         // 256*13

    int tid = threadIdx.x;
    int q = blockIdx.z, ns = blockIdx.y;

    for (int i = tid; i < 576; i += 256) {
        int rf = i / 18, cn = i % 18;
        int ch = ((q * RFN + rf) * NSS + ns) * CNN + cn;
        sSc[i] = g_scale[ch];
        sSh[i] = g_shift[ch];
    }
    for (int i = tid; i < 4608; i += 256) sW1s[i] = w1s[(i & 63) * 72 + (i >> 6)];
    for (int i = tid; i < 4096; i += 256) sW2s[i] = w2s[i];
    for (int i = tid; i < 768;  i += 256) sW1c[i] = w1c[(i & 63) * 12 + (i >> 6)];
    for (int i = tid; i < 4096; i += 256) sW2c[i] = w2c[i];
    if (tid < 64) {
        sB1s[tid] = b1s[tid]; sB2s[tid] = b2s[tid];
        sB1c[tid] = b1c[tid]; sB2c[tid] = b2c[tid];
    }
    __syncthreads();

    int hw = blockIdx.x * 256 + tid;
    int cbase = (q * (RFN * NSS * CNN) + ns * CNN) * HWSZ + hw;

    // ---- phase 1: ref score per rfn + top-4 (stable, strict >) ----
    float v0 = -3.4e38f, v1 = v0, v2 = v0, v3 = v0;
    int i0 = 0, i1 = 0, i2 = 0, i3 = 0;
#pragma unroll 2
    for (int rf = 0; rf < RFN; rf++) {
        const float* cp = corr + cbase + rf * (NSS * CNN) * HWSZ;
        float s = 0.f;
#pragma unroll
        for (int cn = 0; cn < CNN; cn++)
            s += fmaf(cp[cn * HWSZ], sSc[rf * 18 + cn], sSh[rf * 18 + cn]);
        if (s > v0)      { v3=v2;i3=i2; v2=v1;i2=i1; v1=v0;i1=i0; v0=s;i0=rf; }
        else if (s > v1) { v3=v2;i3=i2; v2=v1;i2=i1; v1=s;i1=rf; }
        else if (s > v2) { v3=v2;i3=i2; v2=s;i2=rf; }
        else if (s > v3) { v3=s;i3=rf; }
    }
    unsigned packed = (unsigned)i0 | ((unsigned)i1 << 8) | ((unsigned)i2 << 16) | ((unsigned)i3 << 24);

    // ---- phase 2: gather + 72->64 matvec with f32x2 ----
    unsigned long long h2[32];
#pragma unroll
    for (int j = 0; j < 32; j++) h2[j] = pk2b(sB1s[2*j], sB1s[2*j+1]);
#pragma unroll
    for (int i = 0; i < 12; i++) sLvl[tid * 13 + i] = 0.f;

#pragma unroll 1
    for (int k = 0; k < KNN; k++) {
        int rf = (packed >> (k * 8)) & 255;
        const float* cp = corr + cbase + rf * (NSS * CNN) * HWSZ;
        int sb = rf * 18;
#pragma unroll
        for (int cn = 0; cn < CNN; cn++) {
            float xn = fmaf(cp[cn * HWSZ], sSc[sb + cn], sSh[sb + cn]);
            sLvl[tid * 13 + k * 3 + cn / 6] += xn;
            unsigned long long xx = pk2(xn);
            const float4* wp = (const float4*)&sW1s[(k * 18 + cn) * 64];
#pragma unroll
            for (int jj = 0; jj < 16; jj++) {
                F4U2 w; w.f4 = wp[jj];
                h2[2*jj]   = fma2(xx, w.u[0], h2[2*jj]);
                h2[2*jj+1] = fma2(xx, w.u[1], h2[2*jj+1]);
            }
        }
    }
#pragma unroll
    for (int j = 0; j < 32; j++) {
        float2 v = up2(h2[j]);
        h2[j] = pk2b(fmaxf(v.x, 0.f), fmaxf(v.y, 0.f));
    }

    // ---- phase 3: 64->64, write scale-branch features ----
    int obase = ((q * NSS + ns) * 64) * HWSZ + hw;
#pragma unroll 2
    for (int o = 0; o < 64; o += 4) {
        unsigned long long a0 = 0, a1 = 0, a2 = 0, a3 = 0;
        const float4* r0 = (const float4*)&sW2s[(o+0) * 64];
        const float4* r1 = (const float4*)&sW2s[(o+1) * 64];
        const float4* r2 = (const float4*)&sW2s[(o+2) * 64];
        const float4* r3 = (const float4*)&sW2s[(o+3) * 64];
#pragma unroll
        for (int jj = 0; jj < 16; jj++) {
            F4U2 w0, w1, w2, w3;
            w0.f4 = r0[jj]; w1.f4 = r1[jj]; w2.f4 = r2[jj]; w3.f4 = r3[jj];
            a0 = fma2(h2[2*jj], w0.u[0], a0); a0 = fma2(h2[2*jj+1], w0.u[1], a0);
            a1 = fma2(h2[2*jj], w1.u[0], a1); a1 = fma2(h2[2*jj+1], w1.u[1], a1);
            a2 = fma2(h2[2*jj], w2.u[0], a2); a2 = fma2(h2[2*jj+1], w2.u[1], a2);
            a3 = fma2(h2[2*jj], w3.u[0], a3); a3 = fma2(h2[2*jj+1], w3.u[1], a3);
        }
        float2 s0 = up2(a0), s1 = up2(a1), s2 = up2(a2), s3 = up2(a3);
        g_ys[obase + (o+0) * HWSZ] = s0.x + s0.y + sB2s[o+0];
        g_ys[obase + (o+1) * HWSZ] = s1.x + s1.y + sB2s[o+1];
        g_ys[obase + (o+2) * HWSZ] = s2.x + s2.y + sB2s[o+2];
        g_ys[obase + (o+3) * HWSZ] = s3.x + s3.y + sB2s[o+3];
    }

    // ---- phase 4: score branch 12->64 ----
#pragma unroll
    for (int j = 0; j < 32; j++) h2[j] = pk2b(sB1c[2*j], sB1c[2*j+1]);
#pragma unroll 1
    for (int i = 0; i < 12; i++) {
        float xv = sLvl[tid * 13 + i] * (1.0f / 6.0f);
        unsigned long long xx = pk2(xv);
        const float4* wp = (const float4*)&sW1c[i * 64];
#pragma unroll
        for (int jj = 0; jj < 16; jj++) {
            F4U2 w; w.f4 = wp[jj];
            h2[2*jj]   = fma2(xx, w.u[0], h2[2*jj]);
            h2[2*jj+1] = fma2(xx, w.u[1], h2[2*jj+1]);
        }
    }
#pragma unroll
    for (int j = 0; j < 32; j++) {
        float2 v = up2(h2[j]);
        h2[j] = pk2b(fmaxf(v.x, 0.f), fmaxf(v.y, 0.f));
    }

    // ---- phase 5: 64->64, write score-branch features ----
#pragma unroll 2
    for (int o = 0; o < 64; o += 4) {
        unsigned long long a0 = 0, a1 = 0, a2 = 0, a3 = 0;
        const float4* r0 = (const float4*)&sW2c[(o+0) * 64];
        const float4* r1 = (const float4*)&sW2c[(o+1) * 64];
        const float4* r2 = (const float4*)&sW2c[(o+2) * 64];
        const float4* r3 = (const float4*)&sW2c[(o+3) * 64];
#pragma unroll
        for (int jj = 0; jj < 16; jj++) {
            F4U2 w0, w1, w2, w3;
            w0.f4 = r0[jj]; w1.f4 = r1[jj]; w2.f4 = r2[jj]; w3.f4 = r3[jj];
            a0 = fma2(h2[2*jj], w0.u[0], a0); a0 = fma2(h2[2*jj+1], w0.u[1], a0);
            a1 = fma2(h2[2*jj], w1.u[0], a1); a1 = fma2(h2[2*jj+1], w1.u[1], a1);
            a2 = fma2(h2[2*jj], w2.u[0], a2); a2 = fma2(h2[2*jj+1], w2.u[1], a2);
            a3 = fma2(h2[2*jj], w3.u[0], a3); a3 = fma2(h2[2*jj+1], w3.u[1], a3);
        }
        float2 s0 = up2(a0), s1 = up2(a1), s2 = up2(a2), s3 = up2(a3);
        g_yc[obase + (o+0) * HWSZ] = s0.x + s0.y + sB2c[o+0];
        g_yc[obase + (o+1) * HWSZ] = s1.x + s1.y + sB2c[o+1];
        g_yc[obase + (o+2) * HWSZ] = s2.x + s2.y + sB2c[o+2];
        g_yc[obase + (o+3) * HWSZ] = s3.x + s3.y + sB2c[o+3];
    }
}

// ---------------- 3) max over ns, float4 ----------------
__global__ void maxns_kernel() {
    int idx = (blockIdx.x * 256 + threadIdx.x) << 2;
    int q = idx >> 18;
    int within = idx & ((1 << 18) - 1);
    int base = (q << 20) + within;
    float4 a = *(const float4*)&g_ys[base];
    float4 b = *(const float4*)&g_yc[base];
#pragma unroll
    for (int ns = 1; ns < NSS; ns++) {
        float4 ya = *(const float4*)&g_ys[base + (ns << 18)];
        float4 yb = *(const float4*)&g_yc[base + (ns << 18)];
        a.x = fmaxf(a.x, ya.x); a.y = fmaxf(a.y, ya.y);
        a.z = fmaxf(a.z, ya.z); a.w = fmaxf(a.w, ya.w);
        b.x = fmaxf(b.x, yb.x); b.y = fmaxf(b.y, yb.y);
        b.z = fmaxf(b.z, yb.z); b.w = fmaxf(b.w, yb.w);
    }
    *(float4*)&g_xs[idx] = a;
    *(float4*)&g_xc[idx] = b;
}

// ---------------- 4) conv3x3, batched heads, 8px x 8out threads (R12 exact) ----------------
struct HeadIO {
    const float* in;
    const float* w;
    const float* b;
    float* out;
    int cout;
};

#define CICH 16
#define TROW 20

__global__ __launch_bounds__(128) void conv_mid_kernel(HeadIO a0, HeadIO a1, HeadIO a2) {
    __shared__ __align__(16) float tile[CICH * 18 * TROW];
    __shared__ __align__(16) float wsm[CICH * 288];

    int tid = threadIdx.x;
    int bz = blockIdx.z;
    int head = bz >> 3;
    int rem = bz & 7;
    int q = rem >> 1;
    int co0 = (rem & 1) * 32;
    HeadIO io = (head == 0) ? a0 : ((head == 1) ? a1 : a2);

    int bx = blockIdx.x * 16, by = blockIdx.y * 16;

    int og = tid >> 5;
    int pg = tid & 31;
    int ty = pg >> 1;
    int tx = (pg & 1) << 3;

    unsigned long long acc[8][4];
#pragma unroll
    for (int p = 0; p < 8; p++)
#pragma unroll
        for (int c = 0; c < 4; c++) acc[p][c] = 0ull;

#pragma unroll 1
    for (int cc = 0; cc < 64 / CICH; cc++) {
        if (cc) __syncthreads();
        for (int i = tid; i < CICH * 324; i += 128) {
            int ci = i / 324;
            int r = i - ci * 324;
            int yy = r / 18, xx = r - yy * 18;
            int gy = by + yy - 1, gx = bx + xx - 1;
            float v = 0.f;
            if ((unsigned)gy < 64u && (unsigned)gx < 64u)
                v = io.in[(q * 64 + cc * CICH + ci) * HWSZ + gy * WW + gx];
            tile[ci * (18 * TROW) + yy * TROW + xx] = v;
        }
        for (int i = tid; i < CICH * 288; i += 128) {
            int co = i & 31;
            int tap = (i >> 5) % 9;
            int ci = i / 288;
            wsm[i] = io.w[((co0 + co) * 64 + cc * CICH + ci) * 9 + tap];
        }
        __syncthreads();

#pragma unroll 1
        for (int ci = 0; ci < CICH; ci++) {
            const float* tt = &tile[ci * (18 * TROW) + ty * TROW + tx];
            unsigned long long x2[3][10];
#pragma unroll
            for (int dy = 0; dy < 3; dy++) {
                float4 ra = *(const float4*)&tt[dy * TROW];
                float4 rb = *(const float4*)&tt[dy * TROW + 4];
                float s8 = tt[dy * TROW + 8];
                float s9 = tt[dy * TROW + 9];
                x2[dy][0] = pk2(ra.x); x2[dy][1] = pk2(ra.y);
                x2[dy][2] = pk2(ra.z); x2[dy][3] = pk2(ra.w);
                x2[dy][4] = pk2(rb.x); x2[dy][5] = pk2(rb.y);
                x2[dy][6] = pk2(rb.z); x2[dy][7] = pk2(rb.w);
                x2[dy][8] = pk2(s8);   x2[dy][9] = pk2(s9);
            }
            const float4* wp = (const float4*)&wsm[ci * 288 + og * 8];
#pragma unroll
            for (int tap = 0; tap < 9; tap++) {
                F4U2 wa, wb;
                wa.f4 = wp[tap * 8];
                wb.f4 = wp[tap * 8 + 1];
                int dy = tap / 3, dx = tap % 3;
#pragma unroll
                for (int p = 0; p < 8; p++) {
                    unsigned long long xv = x2[dy][dx + p];
                    acc[p][0] = fma2(xv, wa.u[0], acc[p][0]);
                    acc[p][1] = fma2(xv, wa.u[1], acc[p][1]);
                    acc[p][2] = fma2(xv, wb.u[0], acc[p][2]);
                    acc[p][3] = fma2(xv, wb.u[1], acc[p][3]);
                }
            }
        }
    }

    int ob = (q * 64 + co0 + og * 8) * HWSZ + (by + ty) * WW + bx + tx;
#pragma unroll
    for (int pair = 0; pair < 4; pair++) {
        float blo = io.b[co0 + og * 8 + pair * 2];
        float bhi = io.b[co0 + og * 8 + pair * 2 + 1];
        float2 v[8];
#pragma unroll
        for (int p = 0; p < 8; p++) v[p] = up2(acc[p][pair]);
        float4 lo0 = make_float4(fmaxf(v[0].x + blo, 0.f), fmaxf(v[1].x + blo, 0.f),
                                 fmaxf(v[2].x + blo, 0.f), fmaxf(v[3].x + blo, 0.f));
        float4 lo1 = make_float4(fmaxf(v[4].x + blo, 0.f), fmaxf(v[5].x + blo, 0.f),
                                 fmaxf(v[6].x + blo, 0.f), fmaxf(v[7].x + blo, 0.f));
        float4 hi0 = make_float4(fmaxf(v[0].y + bhi, 0.f), fmaxf(v[1].y + bhi, 0.f),
                                 fmaxf(v[2].y + bhi, 0.f), fmaxf(v[3].y + bhi, 0.f));
        float4 hi1 = make_float4(fmaxf(v[4].y + bhi, 0.f), fmaxf(v[5].y + bhi, 0.f),
                                 fmaxf(v[6].y + bhi, 0.f), fmaxf(v[7].y + bhi, 0.f));
        *(float4*)&io.out[ob + (pair * 2) * HWSZ]     = lo0;
        *(float4*)&io.out[ob + (pair * 2) * HWSZ + 4] = lo1;
        *(float4*)&io.out[ob + (pair * 2 + 1) * HWSZ]     = hi0;
        *(float4*)&io.out[ob + (pair * 2 + 1) * HWSZ + 4] = hi1;
    }
}

__global__ __launch_bounds__(256) void conv_last_kernel(HeadIO a0, HeadIO a1, HeadIO a2) {
    __shared__ float tile[CICH * 342];
    __shared__ float wsm[CICH * 18];

    int tid = threadIdx.x;
    int bz = blockIdx.z;
    int head = bz >> 2;
    int q = bz & 3;
    HeadIO io = (head == 0) ? a0 : ((head == 1) ? a1 : a2);
    int Cout = io.cout;

    int bx = blockIdx.x * 16, by = blockIdx.y * 16;
    int tx = tid & 15, ty = tid >> 4;
    float acc0 = 0.f, acc1 = 0.f;

#pragma unroll 1
    for (int cc = 0; cc < 64 / CICH; cc++) {
        if (cc) __syncthreads();
        for (int i = tid; i < CICH * 324; i += 256) {
            int ci = i / 324;
            int r = i - ci * 324;
            int yy = r / 18, xx = r - yy * 18;
            int gy = by + yy - 1, gx = bx + xx - 1;
            float v = 0.f;
            if ((unsigned)gy < 64u && (unsigned)gx < 64u)
                v = io.in[(q * 64 + cc * CICH + ci) * HWSZ + gy * WW + gx];
            tile[ci * 342 + yy * 19 + xx] = v;
        }
        for (int i = tid; i < CICH * 18; i += 256) {
            int co = i & 1;
            int tap = (i >> 1) % 9;
            int ci = i / 18;
            wsm[i] = (co < Cout) ? io.w[(co * 64 + cc * CICH + ci) * 9 + tap] : 0.f;
        }
        __syncthreads();

#pragma unroll 1
        for (int ci = 0; ci < CICH; ci++) {
            const float* tt = &tile[ci * 342 + ty * 19 + tx];
            const float* wp = &wsm[ci * 18];
#pragma unroll
            for (int tap = 0; tap < 9; tap++) {
                float av = tt[(tap / 3) * 19 + (tap % 3)];
                acc0 = fmaf(av, wp[tap * 2 + 0], acc0);
                acc1 = fmaf(av, wp[tap * 2 + 1], acc1);
            }
        }
    }

    int gy = by + ty, gx = bx + tx;
    io.out[(q * Cout + 0) * HWSZ + gy * WW + gx] = acc0 + io.b[0];
    if (Cout > 1)
        io.out[(q * Cout + 1) * HWSZ + gy * WW + gx] = acc1 + io.b[1];
}

// ---------------- 5) argmax + pos/scl ----------------
__global__ void finalize_kernel(float* out) {
    __shared__ float sv[256];
    __shared__ int si[256];
    int q = blockIdx.x, tid = threadIdx.x;
    const float* sc = out + OFF_SCORES + q * HWSZ;
    float bv = -3.4e38f;
    int bi = 0;
    for (int i = tid; i < HWSZ; i += 256) {
        float v = sc[i];
        if (v > bv) { bv = v; bi = i; }
    }
    sv[tid] = bv; si[tid] = bi;
    __syncthreads();
    for (int s = 128; s > 0; s >>= 1) {
        if (tid < s) {
            if (sv[tid + s] > sv[tid] || (sv[tid + s] == sv[tid] && si[tid + s] < si[tid])) {
                sv[tid] = sv[tid + s];
                si[tid] = si[tid + s];
            }
        }
        __syncthreads();
    }
    if (tid == 0) {
        int idx = si[0];
        int sy = idx >> 6, sx = idx & 63;
        float offx = out[OFF_OFFS + (q * 2 + 0) * HWSZ + idx];
        float offy = out[OFF_OFFS + (q * 2 + 1) * HWSZ + idx];
        float sclv = out[OFF_SCALES + q * HWSZ + idx];
        out[OFF_POS + q * 2 + 0] = ((float)sx + offx + 0.5f) * 8.0f - 0.5f;
        out[OFF_POS + q * 2 + 1] = ((float)sy + offy + 0.5f) * 8.0f - 0.5f;
        out[OFF_SCL + q] = exp2f(sclv);
    }
}

// ---------------- launch ----------------
extern "C" void kernel_launch(void* const* d_in, const int* in_sizes, int n_in,
                              void* d_out, int out_size) {
    const float* corr = (const float*)d_in[0];
    float* out = (float*)d_out;

    float *xs_p, *xc_p, *t1_p, *t2_p;
    cudaGetSymbolAddress((void**)&xs_p, g_xs);
    cudaGetSymbolAddress((void**)&xc_p, g_xc);
    cudaGetSymbolAddress((void**)&t1_p, g_t1);
    cudaGetSymbolAddress((void**)&t2_p, g_t2);
    const int HSZ = QN * 64 * HWSZ;

    const int PIX_SMEM = (576*2 + 4608 + 4096 + 768 + 4096 + 256 + 256*13) * 4;
    cudaFuncSetAttribute(pixel_kernel, cudaFuncAttributeMaxDynamicSharedMemorySize, PIX_SMEM);

    stats_kernel<<<QN * RFN * NSS * CNN, 256>>>(corr);

    pixel_kernel<<<dim3(16, NSS, QN), 256, PIX_SMEM>>>(
        corr, (const float*)d_in[1], (const float*)d_in[2],
        (const float*)d_in[3], (const float*)d_in[4],
        (const float*)d_in[5], (const float*)d_in[6],
        (const float*)d_in[7], (const float*)d_in[8]);

    maxns_kernel<<<1024, 256>>>();

    {
        HeadIO h0 = { xs_p, (const float*)d_in[9],  (const float*)d_in[10], t1_p + 0*HSZ, 64 };
        HeadIO h1 = { xc_p, (const float*)d_in[15], (const float*)d_in[16], t1_p + 1*HSZ, 64 };
        HeadIO h2 = { xc_p, (const float*)d_in[21], (const float*)d_in[22], t1_p + 2*HSZ, 64 };
        conv_mid_kernel<<<dim3(4, 4, 24), 128>>>(h0, h1, h2);
    }
    {
        HeadIO h0 = { t1_p + 0*HSZ, (const float*)d_in[11], (const float*)d_in[12], t2_p + 0*HSZ, 64 };
        HeadIO h1 = { t1_p + 1*HSZ, (const float*)d_in[17], (const float*)d_in[18], t2_p + 1*HSZ, 64 };
        HeadIO h2 = { t1_p + 2*HSZ, (const float*)d_in[23], (const float*)d_in[24], t2_p + 2*HSZ, 64 };
        conv_mid_kernel<<<dim3(4, 4, 24), 128>>>(h0, h1, h2);
    }
    {
        HeadIO h0 = { t2_p + 0*HSZ, (const float*)d_in[13], (const float*)d_in[14], out + OFF_SCALES, 1 };
        HeadIO h1 = { t2_p + 1*HSZ, (const float*)d_in[19], (const float*)d_in[20], out + OFF_OFFS, 2 };
        HeadIO h2 = { t2_p + 2*HSZ, (const float*)d_in[25], (const float*)d_in[26], out + OFF_SCORES, 1 };
        conv_last_kernel<<<dim3(4, 4, 12), 256>>>(h0, h1, h2);
    }

    finalize_kernel<<<QN, 256>>>(out);
}